// round 1
// baseline (speedup 1.0000x reference)
#include <cuda_runtime.h>
#include <cstdint>

#define NBINS 256
#define THREADS 256
#define ELEMS_PER_BATCH (256*32*32)          // 262144
#define INT4_PER_BATCH  (ELEMS_PER_BATCH/4)  // 65536
#define INT4_PER_THREAD (INT4_PER_BATCH/THREADS) // 256
#define UNROLL 8
#define ITERS (INT4_PER_THREAD/UNROLL)       // 32
#define HIST_WORDS (NBINS*128)               // 32768 u32 = 128 KB

__global__ __launch_bounds__(THREADS, 1)
void hist_mode_kernel(const int* __restrict__ in, float* __restrict__ out) {
    extern __shared__ unsigned int hist32[];          // [NBINS][128] u32 = 128KB
    unsigned short* hist16 = (unsigned short*)hist32; // [NBINS][256] u16

    const int tid = threadIdx.x;
    const int w = tid >> 5;
    const int l = tid & 31;

    // zero the histogram
    #pragma unroll 4
    for (int i = tid; i < HIST_WORDS; i += THREADS) hist32[i] = 0u;
    __syncthreads();

    // Per-thread 16-bit slot inside each bin's 256-entry row.
    // word index within row = (w/2)*32 + l  -> bank = l (conflict-free, bin-independent)
    // half = w & 1 (warps 2k and 2k+1 share words in different halves: no race)
    const int slot = ((((w >> 1) * 32) + l) << 1) | (w & 1);

    const int4* base = (const int4*)in + (size_t)blockIdx.x * INT4_PER_BATCH;

    // software-pipelined load: 8 int4 (32 elements) in flight per thread
    int4 buf[UNROLL];
    #pragma unroll
    for (int u = 0; u < UNROLL; u++)
        buf[u] = base[u * THREADS + tid];

    for (int it = 0; it < ITERS; it++) {
        int4 nxt[UNROLL];
        const bool more = (it + 1 < ITERS);
        if (more) {
            const int4* p = base + (it + 1) * (UNROLL * THREADS);
            #pragma unroll
            for (int u = 0; u < UNROLL; u++)
                nxt[u] = p[u * THREADS + tid];
        }
        #pragma unroll
        for (int u = 0; u < UNROLL; u++) {
            const int b0 = buf[u].x & 255;
            const int b1 = buf[u].y & 255;
            const int b2 = buf[u].z & 255;
            const int b3 = buf[u].w & 255;
            unsigned short* p0 = hist16 + b0 * 256 + slot;
            unsigned short* p1 = hist16 + b1 * 256 + slot;
            unsigned short* p2 = hist16 + b2 * 256 + slot;
            unsigned short* p3 = hist16 + b3 * 256 + slot;
            // load ALL counters before ANY store; fix intra-quad duplicates so the
            // last (program-order) store to a duplicated bin carries the full count.
            const unsigned int u0 = *p0;
            const unsigned int u1 = *p1;
            const unsigned int u2 = *p2;
            const unsigned int u3 = *p3;
            const unsigned int d1 = (unsigned)(b1 == b0);
            const unsigned int d2 = (unsigned)(b2 == b0) + (unsigned)(b2 == b1);
            const unsigned int d3 = (unsigned)(b3 == b0) + (unsigned)(b3 == b1) + (unsigned)(b3 == b2);
            *p0 = (unsigned short)(u0 + 1u);
            *p1 = (unsigned short)(u1 + 1u + d1);
            *p2 = (unsigned short)(u2 + 1u + d2);
            *p3 = (unsigned short)(u3 + 1u + d3);
        }
        if (more) {
            #pragma unroll
            for (int u = 0; u < UNROLL; u++) buf[u] = nxt[u];
        }
    }
    __syncthreads();

    // Per-bin sum: thread tid owns bin tid; rotated word index -> conflict-free.
    unsigned int total = 0;
    const unsigned int* row = hist32 + tid * 128;
    #pragma unroll 8
    for (int j = 0; j < 128; j++) {
        const unsigned int idx = (unsigned)(tid + j) & 127u;
        const unsigned int v = row[idx];
        total += (v & 0xFFFFu) + (v >> 16);
    }

    // Block max-reduce over 256 per-bin totals.
    unsigned int m = total;
    #pragma unroll
    for (int off = 16; off > 0; off >>= 1)
        m = max(m, __shfl_xor_sync(0xFFFFFFFFu, m, off));
    __syncthreads();                 // done with hist32 contents; reuse it
    if (l == 0) hist32[w] = m;
    __syncthreads();
    if (tid == 0) {
        unsigned int mm = hist32[0];
        #pragma unroll
        for (int i = 1; i < THREADS / 32; i++) mm = max(mm, hist32[i]);
        out[blockIdx.x] = (float)mm;
    }
}

extern "C" void kernel_launch(void* const* d_in, const int* in_sizes, int n_in,
                              void* d_out, int out_size) {
    const int* in = (const int*)d_in[0];
    float* out = (float*)d_out;
    const int B = out_size; // 128 batch elements, one block each

    const size_t smem = HIST_WORDS * sizeof(unsigned int); // 131072 B
    cudaFuncSetAttribute(hist_mode_kernel,
                         cudaFuncAttributeMaxDynamicSharedMemorySize, (int)smem);
    hist_mode_kernel<<<B, THREADS, smem>>>(in, out);
}

// round 2
// speedup vs baseline: 1.1317x; 1.1317x over previous
#include <cuda_runtime.h>
#include <cstdint>

#define NBINS 256
#define THREADS 512
#define ELEMS_PER_BATCH (256*32*32)            // 262144
#define I4_PER_BATCH    (ELEMS_PER_BATCH/4)    // 65536
#define I4_PER_THREAD   (I4_PER_BATCH/THREADS) // 128
#define UNROLL 8
#define CHUNKS 4
#define GROUPS (I4_PER_THREAD/UNROLL)          // 16 groups of 8 int4
#define GROUPS_PER_CHUNK (GROUPS/CHUNKS)       // 4
#define HIST_WORDS (NBINS*128)                 // 32768 u32 = 128 KB (256 bins x 512 u8 slots)

__global__ __launch_bounds__(THREADS, 1)
void hist_mode_kernel(const int* __restrict__ in, float* __restrict__ out) {
    extern __shared__ unsigned int hist32[];       // [NBINS][128] u32 view
    unsigned char* hist8 = (unsigned char*)hist32; // [NBINS][512] u8 slots

    const int tid = threadIdx.x;
    const int w = tid >> 5;
    const int l = tid & 31;

    // zero histogram: 32768 words / 512 threads = 64 words each
    {
        uint4* z = (uint4*)hist32;
        #pragma unroll
        for (int i = 0; i < HIST_WORDS / 4 / THREADS; i++)
            z[i * THREADS + tid] = make_uint4(0, 0, 0, 0);
    }
    __syncthreads();

    // Byte slot within each bin's 512-byte row:
    //   s = (w>>2)*128 + l*4 + (w&3)
    // word index within row = (w>>2)*32 + l  -> bank = l (conflict-free, bin-independent)
    // warps w with same (w>>2) share words in distinct bytes (byte-enable, no race)
    const int slot = ((w >> 2) << 7) + (l << 2) + (w & 3);

    // Flush assignment: thread t accumulates bin (t&255), half (t>>8) of the row.
    const int fbin  = tid & 255;
    const int fhalf = tid >> 8;
    unsigned int* frow = hist32 + fbin * 128 + fhalf * 64;
    unsigned int acc = 0;

    const int4* base = (const int4*)in + (size_t)blockIdx.x * I4_PER_BATCH;

    // software pipeline: one 8-int4 group in flight
    int4 buf[UNROLL];
    #pragma unroll
    for (int u = 0; u < UNROLL; u++)
        buf[u] = base[u * THREADS + tid];

    for (int chunk = 0; chunk < CHUNKS; chunk++) {
        for (int it = 0; it < GROUPS_PER_CHUNK; it++) {
            const int g = chunk * GROUPS_PER_CHUNK + it;
            int4 nxt[UNROLL];
            const bool more = (g + 1 < GROUPS);
            if (more) {
                const int4* p = base + (g + 1) * (UNROLL * THREADS) + tid;
                #pragma unroll
                for (int u = 0; u < UNROLL; u++)
                    nxt[u] = p[u * THREADS];
            }
            #pragma unroll
            for (int u = 0; u < UNROLL; u++) {
                const int b0 = buf[u].x & 255;
                const int b1 = buf[u].y & 255;
                const int b2 = buf[u].z & 255;
                const int b3 = buf[u].w & 255;
                unsigned char* p0 = hist8 + (b0 << 9) + slot;
                unsigned char* p1 = hist8 + (b1 << 9) + slot;
                unsigned char* p2 = hist8 + (b2 << 9) + slot;
                unsigned char* p3 = hist8 + (b3 << 9) + slot;
                // load all counters before any store; fix intra-quad duplicates so
                // the last (program-order) store to a duplicated bin carries the
                // full count (same-thread same-address smem ops are ordered).
                const unsigned int u0 = *p0;
                const unsigned int u1 = *p1;
                const unsigned int u2 = *p2;
                const unsigned int u3 = *p3;
                const unsigned int d1 = (unsigned)(b1 == b0);
                const unsigned int d2 = (unsigned)(b2 == b0) + (unsigned)(b2 == b1);
                const unsigned int d3 = (unsigned)(b3 == b0) + (unsigned)(b3 == b1) + (unsigned)(b3 == b2);
                *p0 = (unsigned char)(u0 + 1u);
                *p1 = (unsigned char)(u1 + 1u + d1);
                *p2 = (unsigned char)(u2 + 1u + d2);
                *p3 = (unsigned char)(u3 + 1u + d3);
            }
            if (more) {
                #pragma unroll
                for (int u = 0; u < UNROLL; u++) buf[u] = nxt[u];
            }
        }
        // Flush this chunk's u8 counts into the per-thread register accumulator.
        // Max per-slot count per chunk = 128 elements < 255: no overflow.
        __syncthreads();
        #pragma unroll 16
        for (int j = 0; j < 64; j++) {
            const int idx = (j + fbin) & 63;   // bank-rotated: conflict-free
            const unsigned int v = frow[idx];
            acc = __dp4a(v, 0x01010101u, acc); // acc += sum of 4 bytes
            frow[idx] = 0u;
        }
        __syncthreads();
    }

    // acc = partial total for (fbin, fhalf). Combine halves + block max.
    hist32[tid] = acc;
    __syncthreads();
    if (tid < NBINS) {
        unsigned int tot = hist32[tid] + hist32[tid + NBINS];
        unsigned int m = tot;
        #pragma unroll
        for (int off = 16; off > 0; off >>= 1)
            m = max(m, __shfl_xor_sync(0xFFFFFFFFu, m, off));
        __syncthreads();
        if (l == 0) hist32[w] = m;
        __syncthreads();
        if (tid == 0) {
            unsigned int mm = hist32[0];
            #pragma unroll
            for (int i = 1; i < NBINS / 32; i++) mm = max(mm, hist32[i]);
            out[blockIdx.x] = (float)mm;
        }
    } else {
        __syncthreads();
        __syncthreads();
    }
}

extern "C" void kernel_launch(void* const* d_in, const int* in_sizes, int n_in,
                              void* d_out, int out_size) {
    const int* in = (const int*)d_in[0];
    float* out = (float*)d_out;
    const int B = out_size; // 128 batch elements, one block each

    const size_t smem = HIST_WORDS * sizeof(unsigned int); // 131072 B
    cudaFuncSetAttribute(hist_mode_kernel,
                         cudaFuncAttributeMaxDynamicSharedMemorySize, (int)smem);
    hist_mode_kernel<<<B, THREADS, smem>>>(in, out);
}

// round 3
// speedup vs baseline: 1.2905x; 1.1404x over previous
#include <cuda_runtime.h>
#include <cstdint>

#define NBINS 256
#define THREADS 512
#define ELEMS_PER_BATCH (256*32*32)            // 262144
#define I4_PER_BATCH    (ELEMS_PER_BATCH/4)    // 65536
#define I4_PER_THREAD   (I4_PER_BATCH/THREADS) // 128
#define UNROLL 8
#define GROUPS (I4_PER_THREAD/UNROLL)          // 16 groups of 8 int4
#define HIST_WORDS (NBINS*128)                 // 32768 u32 = 128 KB (256 bins x 512 u8 slots)

__global__ __launch_bounds__(THREADS, 1)
void hist_mode_kernel(const int* __restrict__ in, float* __restrict__ out) {
    extern __shared__ unsigned int hist32[];       // [NBINS][128] u32 view
    unsigned char* hist8 = (unsigned char*)hist32; // [NBINS][512] u8 slots

    const int tid = threadIdx.x;
    const int w = tid >> 5;
    const int l = tid & 31;

    // zero histogram: 8192 uint4 / 512 threads = 16 each
    {
        uint4* z = (uint4*)hist32;
        #pragma unroll
        for (int i = 0; i < HIST_WORDS / 4 / THREADS; i++)
            z[i * THREADS + tid] = make_uint4(0, 0, 0, 0);
    }
    __syncthreads();

    // Byte slot within each bin's 512-byte row:
    //   s = (w>>2)*128 + l*4 + (w&3)
    // word index within row = (w>>2)*32 + l  -> bank = l (conflict-free, bin-independent)
    // warps with the same (w>>2) share words in distinct bytes (byte-enable, no race)
    const int slot = ((w >> 2) << 7) + (l << 2) + (w & 3);
    unsigned char* const sbase = hist8 + slot;

    const int4* base = (const int4*)in + (size_t)blockIdx.x * I4_PER_BATCH;

    // software pipeline: one 8-int4 group (128 B/thread) in flight
    int4 buf[UNROLL];
    #pragma unroll
    for (int u = 0; u < UNROLL; u++)
        buf[u] = base[u * THREADS + tid];

    for (int g = 0; g < GROUPS; g++) {
        int4 nxt[UNROLL];
        const bool more = (g + 1 < GROUPS);
        if (more) {
            const int4* p = base + (g + 1) * (UNROLL * THREADS) + tid;
            #pragma unroll
            for (int u = 0; u < UNROLL; u++)
                nxt[u] = p[u * THREADS];
        }
        #pragma unroll
        for (int u = 0; u < UNROLL; u++) {
            // inputs are guaranteed in [0,256): the value IS the bin
            const unsigned int x0 = (unsigned int)buf[u].x;
            const unsigned int x1 = (unsigned int)buf[u].y;
            const unsigned int x2 = (unsigned int)buf[u].z;
            const unsigned int x3 = (unsigned int)buf[u].w;
            unsigned char* p0 = sbase + (x0 << 9);
            unsigned char* p1 = sbase + (x1 << 9);
            unsigned char* p2 = sbase + (x2 << 9);
            unsigned char* p3 = sbase + (x3 << 9);
            // Pairwise RMW. Same-thread smem ops execute in program order, so
            // p2/p3 loads observe p0/p1 stores; only the in-flight pair needs a
            // duplicate fix (last store carries the pair's full count).
            const unsigned int a0 = *p0;
            const unsigned int a1 = *p1;
            *p0 = (unsigned char)(a0 + 1u);
            *p1 = (unsigned char)(a1 + 1u + (unsigned)(x0 == x1));
            const unsigned int a2 = *p2;
            const unsigned int a3 = *p3;
            *p2 = (unsigned char)(a2 + 1u);
            *p3 = (unsigned char)(a3 + 1u + (unsigned)(x2 == x3));
        }
        if (more) {
            #pragma unroll
            for (int u = 0; u < UNROLL; u++) buf[u] = nxt[u];
        }
    }
    __syncthreads();

    // Reduction: thread t sums bin (t&255), half (t>>8) of that bin's 128-word
    // row (64 words), 4 u8 counters per word via dp4a. Rotated index -> no
    // bank conflicts.
    const int fbin  = tid & 255;
    const int fhalf = tid >> 8;
    const unsigned int* frow = hist32 + fbin * 128 + fhalf * 64;
    unsigned int acc = 0;
    #pragma unroll 16
    for (int j = 0; j < 64; j++) {
        const int idx = (j + fbin) & 63;
        acc = __dp4a(frow[idx], 0x01010101u, acc);
    }
    __syncthreads();                 // hist contents consumed; reuse smem
    hist32[tid] = acc;
    __syncthreads();

    if (tid < NBINS) {
        const unsigned int tot = hist32[tid] + hist32[tid + NBINS];
        unsigned int m = tot;
        #pragma unroll
        for (int off = 16; off > 0; off >>= 1)
            m = max(m, __shfl_xor_sync(0xFFFFFFFFu, m, off));
        __syncthreads();
        if (l == 0) hist32[w] = m;
        __syncthreads();
        if (tid == 0) {
            unsigned int mm = hist32[0];
            #pragma unroll
            for (int i = 1; i < NBINS / 32; i++) mm = max(mm, hist32[i]);
            out[blockIdx.x] = (float)mm;
        }
    } else {
        __syncthreads();
        __syncthreads();
    }
}

extern "C" void kernel_launch(void* const* d_in, const int* in_sizes, int n_in,
                              void* d_out, int out_size) {
    const int* in = (const int*)d_in[0];
    float* out = (float*)d_out;
    const int B = out_size; // 128 batch elements, one block each

    const size_t smem = HIST_WORDS * sizeof(unsigned int); // 131072 B
    cudaFuncSetAttribute(hist_mode_kernel,
                         cudaFuncAttributeMaxDynamicSharedMemorySize, (int)smem);
    hist_mode_kernel<<<B, THREADS, smem>>>(in, out);
}